// round 2
// baseline (speedup 1.0000x reference)
#include <cuda_runtime.h>

// ---------------------------------------------------------------------------
// NSA forward, fp32 reference-accurate implementation.
// Pipeline: GEMM(q,k,v,gates) -> RoPE -> block means -> compressed attn
//           (+ importance + stable top-4) -> selected attn -> window attn ->
//           gated combine (accumulated in g_ocomb) -> output GEMM.
// ---------------------------------------------------------------------------

namespace {
constexpr int S_ = 1024;
constexpr int D_ = 2048;
constexpr int H_ = 32;
constexpr int G_ = 2;
constexpr int HG_ = 16;      // heads per group
constexpr int DQ_ = 128;
constexpr int DV_ = 128;
constexpr int BLK_ = 64;
constexpr int C_ = 16;       // S / BLK
constexpr int TOPN_ = 4;
constexpr int WIN_ = 256;
constexpr float SCALE_ = 0.08838834764831845f;  // 1/sqrt(128)
}

// Scratch (device globals; no allocation allowed)
__device__ float g_qraw[S_ * H_ * DQ_];
__device__ float g_q[S_ * H_ * DQ_];
__device__ float g_kraw[S_ * G_ * DQ_];
__device__ float g_k[S_ * G_ * DQ_];
__device__ float g_v[S_ * G_ * DV_];
__device__ float g_gates[S_ * H_ * 3];
__device__ float g_kc[C_ * G_ * DQ_];
__device__ float g_vc[C_ * G_ * DV_];
__device__ int   g_idx[S_ * G_ * TOPN_];
__device__ float g_ocomb[S_ * H_ * DV_];

__device__ __forceinline__ float warp_sum(float v) {
#pragma unroll
    for (int o = 16; o > 0; o >>= 1) v += __shfl_xor_sync(0xffffffffu, v, o);
    return v;
}
__device__ __forceinline__ float warp_max(float v) {
#pragma unroll
    for (int o = 16; o > 0; o >>= 1) v = fmaxf(v, __shfl_xor_sync(0xffffffffu, v, o));
    return v;
}

// ---------------------------------------------------------------------------
// Generic fp32 GEMM: C[M,N] = A[M,K] @ B[K,N], row-major.
// 128x128 tile, BK=8, 256 threads, 8x8 per-thread microtile.
// M must be a multiple of 128, K a multiple of 8; N arbitrary (guarded).
// ---------------------------------------------------------------------------
__global__ __launch_bounds__(256) void gemm128(const float* __restrict__ A,
                                               const float* __restrict__ B,
                                               float* __restrict__ Cm,
                                               int M, int N, int K) {
    __shared__ float As[8][128];
    __shared__ float Bs[8][128];
    const int tid = threadIdx.x;
    const int bm = blockIdx.y * 128;
    const int bn = blockIdx.x * 128;
    const int tx = (tid & 15) * 8;
    const int ty = (tid >> 4) * 8;
    const int arow = tid >> 1;
    const int acol = (tid & 1) * 4;
    const int brow = tid >> 5;
    const int bcol = (tid & 31) * 4;

    float acc[8][8];
#pragma unroll
    for (int i = 0; i < 8; i++)
#pragma unroll
        for (int j = 0; j < 8; j++) acc[i][j] = 0.f;

    for (int k0 = 0; k0 < K; k0 += 8) {
        float4 av = *reinterpret_cast<const float4*>(&A[(size_t)(bm + arow) * K + k0 + acol]);
        As[acol + 0][arow] = av.x;
        As[acol + 1][arow] = av.y;
        As[acol + 2][arow] = av.z;
        As[acol + 3][arow] = av.w;

        float b0 = 0.f, b1 = 0.f, b2 = 0.f, b3 = 0.f;
        const float* Bp = &B[(size_t)(k0 + brow) * N + bn + bcol];
        if (bn + bcol + 3 < N) {
            float4 bv = *reinterpret_cast<const float4*>(Bp);
            b0 = bv.x; b1 = bv.y; b2 = bv.z; b3 = bv.w;
        } else {
            if (bn + bcol + 0 < N) b0 = Bp[0];
            if (bn + bcol + 1 < N) b1 = Bp[1];
            if (bn + bcol + 2 < N) b2 = Bp[2];
            if (bn + bcol + 3 < N) b3 = Bp[3];
        }
        Bs[brow][bcol + 0] = b0;
        Bs[brow][bcol + 1] = b1;
        Bs[brow][bcol + 2] = b2;
        Bs[brow][bcol + 3] = b3;
        __syncthreads();

#pragma unroll
        for (int kk = 0; kk < 8; kk++) {
            float a[8], b[8];
#pragma unroll
            for (int i = 0; i < 8; i++) a[i] = As[kk][ty + i];
#pragma unroll
            for (int j = 0; j < 8; j++) b[j] = Bs[kk][tx + j];
#pragma unroll
            for (int i = 0; i < 8; i++)
#pragma unroll
                for (int j = 0; j < 8; j++) acc[i][j] += a[i] * b[j];
        }
        __syncthreads();
    }

#pragma unroll
    for (int i = 0; i < 8; i++) {
#pragma unroll
        for (int j = 0; j < 8; j++) {
            int col = bn + tx + j;
            if (col < N) Cm[(size_t)(bm + ty + i) * N + col] = acc[i][j];
        }
    }
}

// ---------------------------------------------------------------------------
// RoPE
// ---------------------------------------------------------------------------
__global__ __launch_bounds__(256) void rope_q_kernel(const float* __restrict__ cosp,
                                                     const float* __restrict__ sinp) {
    int i = blockIdx.x * 256 + threadIdx.x;
    if (i >= S_ * H_ * DQ_) return;
    int d = i & 127;
    int s = i >> 12;  // / (H_*DQ_)
    float c = cosp[s * DQ_ + d], sn = sinp[s * DQ_ + d];
    float t = g_qraw[i];
    float rot = (d < 64) ? -g_qraw[i + 64] : g_qraw[i - 64];
    g_q[i] = t * c + rot * sn;
}

__global__ __launch_bounds__(256) void rope_k_kernel(const float* __restrict__ cosp,
                                                     const float* __restrict__ sinp) {
    int i = blockIdx.x * 256 + threadIdx.x;
    if (i >= S_ * G_ * DQ_) return;
    int d = i & 127;
    int s = i >> 8;  // / (G_*DQ_)
    float c = cosp[s * DQ_ + d], sn = sinp[s * DQ_ + d];
    float t = g_kraw[i];
    float rot = (d < 64) ? -g_kraw[i + 64] : g_kraw[i - 64];
    g_k[i] = t * c + rot * sn;
}

__global__ __launch_bounds__(256) void sigmoid_kernel() {
    int i = blockIdx.x * 256 + threadIdx.x;
    if (i >= S_ * H_ * 3) return;
    g_gates[i] = 1.f / (1.f + expf(-g_gates[i]));
}

// Block means of K/V per (c, g, d)
__global__ __launch_bounds__(256) void kcvc_kernel() {
    int i = blockIdx.x * 256 + threadIdx.x;
    if (i >= C_ * G_ * DQ_) return;
    int d = i & 127;
    int g = (i >> 7) & 1;
    int c = i >> 8;
    float sk = 0.f, sv = 0.f;
    for (int j = 0; j < BLK_; j++) {
        int t = c * BLK_ + j;
        sk += g_k[(t * G_ + g) * DQ_ + d];
        sv += g_v[(t * G_ + g) * DV_ + d];
    }
    g_kc[i] = sk * (1.f / 64.f);
    g_vc[i] = sv * (1.f / 64.f);
}

// ---------------------------------------------------------------------------
// Compressed attention + importance + stable top-4 selection.
// One CTA per (s, g); 16 warps = 16 heads; warp lane owns 4 dims.
// ---------------------------------------------------------------------------
__global__ __launch_bounds__(512) void cmp_attn_kernel() {
    const int s = blockIdx.x;
    const int g = blockIdx.y;
    __shared__ float kcs[C_][DQ_];
    __shared__ float vcs[C_][DQ_];
    __shared__ float pw[HG_][C_];
    const int tid = threadIdx.x;

    for (int i = tid; i < C_ * DQ_; i += 512) {
        int c = i >> 7, d = i & 127;
        kcs[c][d] = g_kc[(c * G_ + g) * DQ_ + d];
        vcs[c][d] = g_vc[(c * G_ + g) * DV_ + d];
    }
    __syncthreads();

    const int w = tid >> 5, l = tid & 31;
    const int h = g * HG_ + w;
    const float* qp = &g_q[(s * H_ + h) * DQ_];
    float q0 = qp[l], q1 = qp[l + 32], q2 = qp[l + 64], q3 = qp[l + 96];

    const int ncmp = (s + 1) >> 6;  // # blocks whose last token <= s
    float logit[C_];
#pragma unroll
    for (int c = 0; c < C_; c++) {
        if (c < ncmp) {
            float part = q0 * kcs[c][l] + q1 * kcs[c][l + 32] +
                         q2 * kcs[c][l + 64] + q3 * kcs[c][l + 96];
            logit[c] = warp_sum(part) * SCALE_;
        } else {
            logit[c] = -1e30f;
        }
    }
    float m = -1e30f;
#pragma unroll
    for (int c = 0; c < C_; c++) m = fmaxf(m, logit[c]);
    float p[C_];
    float sum = 0.f;
#pragma unroll
    for (int c = 0; c < C_; c++) {
        float e = (logit[c] > -1e29f) ? expf(logit[c] - m) : 0.f;
        p[c] = e;
        sum += e;
    }
    float inv = (sum > 0.f) ? 1.f / sum : 0.f;

    float o0 = 0.f, o1 = 0.f, o2 = 0.f, o3 = 0.f;
#pragma unroll
    for (int c = 0; c < C_; c++) {
        float pc = p[c] * inv;
        o0 += pc * vcs[c][l];
        o1 += pc * vcs[c][l + 32];
        o2 += pc * vcs[c][l + 64];
        o3 += pc * vcs[c][l + 96];
        if (l == 0) pw[w][c] = pc;  // uniform across lanes after warp_sum
    }
    float gate = g_gates[(s * H_ + h) * 3 + 0];
    float* op = &g_ocomb[(s * H_ + h) * DV_];
    op[l]      = gate * o0;
    op[l + 32] = gate * o1;
    op[l + 64] = gate * o2;
    op[l + 96] = gate * o3;
    __syncthreads();

    if (tid == 0) {
        const int cur = s >> 6;
        float imp[C_];
        for (int c = 0; c < C_; c++) {
            float v;
            if (c > cur) v = -1e9f;                    // invalid
            else if (c == 0 || c == cur) v = 1e9f;     // forced
            else {                                     // deterministic ordered sum
                v = 0.f;
                for (int ww = 0; ww < HG_; ww++) v += pw[ww][c];
            }
            imp[c] = v;
        }
        bool tk[C_];
        for (int c = 0; c < C_; c++) tk[c] = false;
        for (int t = 0; t < TOPN_; t++) {
            float best = -3e38f;
            int bi = 0;
            for (int c = 0; c < C_; c++)
                if (!tk[c] && imp[c] > best) { best = imp[c]; bi = c; }  // strict > == stable top_k
            tk[bi] = true;
            g_idx[(s * G_ + g) * TOPN_ + t] = bi;
        }
    }
}

// ---------------------------------------------------------------------------
// Selected attention over top-4 blocks. One CTA per (s, g), 16 warps.
// K/V staged transposed in smem: kv[d][j] (pad 65 -> conflict-free).
// ---------------------------------------------------------------------------
__global__ __launch_bounds__(512) void slc_attn_kernel() {
    const int s = blockIdx.x, g = blockIdx.y;
    __shared__ float kv[DQ_][BLK_ + 1];
    __shared__ float qsh[HG_][DQ_];
    __shared__ int idxs[TOPN_];
    const int tid = threadIdx.x;

    for (int i = tid; i < HG_ * DQ_; i += 512)
        qsh[i >> 7][i & 127] = g_q[(s * H_ + g * HG_ + (i >> 7)) * DQ_ + (i & 127)];
    if (tid < TOPN_) idxs[tid] = g_idx[(s * G_ + g) * TOPN_ + tid];
    __syncthreads();

    const int w = tid >> 5, l = tid & 31;
    float ls[2 * TOPN_];

#pragma unroll
    for (int n = 0; n < TOPN_; n++) {
        const int t0 = idxs[n] * BLK_;
        for (int i = tid; i < BLK_ * DQ_; i += 512) {
            int j = i >> 7, d = i & 127;
            kv[d][j] = g_k[((t0 + j) * G_ + g) * DQ_ + d];
        }
        __syncthreads();
        float a0 = 0.f, a1 = 0.f;
#pragma unroll 8
        for (int d = 0; d < DQ_; d++) {
            float qd = qsh[w][d];
            a0 += qd * kv[d][l];
            a1 += qd * kv[d][l + 32];
        }
        ls[n * 2 + 0] = (t0 + l <= s) ? a0 * SCALE_ : -1e30f;
        ls[n * 2 + 1] = (t0 + l + 32 <= s) ? a1 * SCALE_ : -1e30f;
        __syncthreads();
    }

    float m = -1e30f;
#pragma unroll
    for (int r = 0; r < 2 * TOPN_; r++) m = fmaxf(m, ls[r]);
    m = warp_max(m);
    float sum = 0.f;
#pragma unroll
    for (int r = 0; r < 2 * TOPN_; r++) {
        ls[r] = (ls[r] > -1e29f) ? expf(ls[r] - m) : 0.f;
        sum += ls[r];
    }
    sum = warp_sum(sum);
    float inv = 1.f / sum;  // cur block always selected -> token s valid -> sum > 0
#pragma unroll
    for (int r = 0; r < 2 * TOPN_; r++) ls[r] *= inv;

    float o0 = 0.f, o1 = 0.f, o2 = 0.f, o3 = 0.f;
#pragma unroll
    for (int n = 0; n < TOPN_; n++) {
        const int t0 = idxs[n] * BLK_;
        for (int i = tid; i < BLK_ * DV_; i += 512) {
            int j = i >> 7, d = i & 127;
            kv[d][j] = g_v[((t0 + j) * G_ + g) * DV_ + d];
        }
        __syncthreads();
#pragma unroll 4
        for (int j = 0; j < BLK_; j++) {
            float pj = __shfl_sync(0xffffffffu, ls[n * 2 + (j >> 5)], j & 31);
            o0 += pj * kv[l][j];
            o1 += pj * kv[l + 32][j];
            o2 += pj * kv[l + 64][j];
            o3 += pj * kv[l + 96][j];
        }
        __syncthreads();
    }

    const int h = g * HG_ + w;
    float gate = g_gates[(s * H_ + h) * 3 + 1];
    float* op = &g_ocomb[(s * H_ + h) * DV_];
    op[l]      += gate * o0;
    op[l + 32] += gate * o1;
    op[l + 64] += gate * o2;
    op[l + 96] += gate * o3;
}

// ---------------------------------------------------------------------------
// Sliding-window attention (window 256 = up to 4 chunks of 64).
// Always processes 4 chunks starting at wstart; invalid keys masked.
// All touched tokens are < S (proved: t <= max(s, 255)).
// ---------------------------------------------------------------------------
__global__ __launch_bounds__(512) void win_attn_kernel() {
    const int s = blockIdx.x, g = blockIdx.y;
    __shared__ float kv[DQ_][BLK_ + 1];
    __shared__ float qsh[HG_][DQ_];
    const int tid = threadIdx.x;

    for (int i = tid; i < HG_ * DQ_; i += 512)
        qsh[i >> 7][i & 127] = g_q[(s * H_ + g * HG_ + (i >> 7)) * DQ_ + (i & 127)];
    __syncthreads();

    const int w = tid >> 5, l = tid & 31;
    const int wstart = (s >= WIN_) ? (s - WIN_ + 1) : 0;
    float ls[8];

#pragma unroll
    for (int n = 0; n < 4; n++) {
        const int t0 = wstart + n * BLK_;
        for (int i = tid; i < BLK_ * DQ_; i += 512) {
            int j = i >> 7, d = i & 127;
            kv[d][j] = g_k[((t0 + j) * G_ + g) * DQ_ + d];
        }
        __syncthreads();
        float a0 = 0.f, a1 = 0.f;
#pragma unroll 8
        for (int d = 0; d < DQ_; d++) {
            float qd = qsh[w][d];
            a0 += qd * kv[d][l];
            a1 += qd * kv[d][l + 32];
        }
        ls[n * 2 + 0] = (t0 + l <= s) ? a0 * SCALE_ : -1e30f;
        ls[n * 2 + 1] = (t0 + l + 32 <= s) ? a1 * SCALE_ : -1e30f;
        __syncthreads();
    }

    float m = -1e30f;
#pragma unroll
    for (int r = 0; r < 8; r++) m = fmaxf(m, ls[r]);
    m = warp_max(m);
    float sum = 0.f;
#pragma unroll
    for (int r = 0; r < 8; r++) {
        ls[r] = (ls[r] > -1e29f) ? expf(ls[r] - m) : 0.f;
        sum += ls[r];
    }
    sum = warp_sum(sum);
    float inv = 1.f / sum;  // token s always inside window
#pragma unroll
    for (int r = 0; r < 8; r++) ls[r] *= inv;

    float o0 = 0.f, o1 = 0.f, o2 = 0.f, o3 = 0.f;
#pragma unroll
    for (int n = 0; n < 4; n++) {
        const int t0 = wstart + n * BLK_;
        for (int i = tid; i < BLK_ * DV_; i += 512) {
            int j = i >> 7, d = i & 127;
            kv[d][j] = g_v[((t0 + j) * G_ + g) * DV_ + d];
        }
        __syncthreads();
#pragma unroll 4
        for (int j = 0; j < BLK_; j++) {
            float pj = __shfl_sync(0xffffffffu, ls[n * 2 + (j >> 5)], j & 31);
            o0 += pj * kv[l][j];
            o1 += pj * kv[l + 32][j];
            o2 += pj * kv[l + 64][j];
            o3 += pj * kv[l + 96][j];
        }
        __syncthreads();
    }

    const int h = g * HG_ + w;
    float gate = g_gates[(s * H_ + h) * 3 + 2];
    float* op = &g_ocomb[(s * H_ + h) * DV_];
    op[l]      += gate * o0;
    op[l + 32] += gate * o1;
    op[l + 64] += gate * o2;
    op[l + 96] += gate * o3;
}

// ---------------------------------------------------------------------------
extern "C" void kernel_launch(void* const* d_in, const int* in_sizes, int n_in,
                              void* d_out, int out_size) {
    const float* x    = (const float*)d_in[0];
    const float* cosp = (const float*)d_in[1];
    const float* sinp = (const float*)d_in[2];
    const float* Wq   = (const float*)d_in[3];
    const float* Wk   = (const float*)d_in[4];
    const float* Wv   = (const float*)d_in[5];
    const float* Wo   = (const float*)d_in[6];
    const float* Wc   = (const float*)d_in[7];
    float* out = (float*)d_out;

    float *p_qraw, *p_kraw, *p_v, *p_gates, *p_ocomb;
    cudaGetSymbolAddress((void**)&p_qraw, g_qraw);
    cudaGetSymbolAddress((void**)&p_kraw, g_kraw);
    cudaGetSymbolAddress((void**)&p_v, g_v);
    cudaGetSymbolAddress((void**)&p_gates, g_gates);
    cudaGetSymbolAddress((void**)&p_ocomb, g_ocomb);

    // Projections
    gemm128<<<dim3(32, 8), 256>>>(x, Wq, p_qraw, S_, H_ * DQ_, D_);
    gemm128<<<dim3(2, 8), 256>>>(x, Wk, p_kraw, S_, G_ * DQ_, D_);
    gemm128<<<dim3(2, 8), 256>>>(x, Wv, p_v, S_, G_ * DV_, D_);
    gemm128<<<dim3(1, 8), 256>>>(x, Wc, p_gates, S_, H_ * 3, D_);

    // RoPE + gates + block means
    rope_q_kernel<<<(S_ * H_ * DQ_) / 256, 256>>>(cosp, sinp);
    rope_k_kernel<<<(S_ * G_ * DQ_) / 256, 256>>>(cosp, sinp);
    sigmoid_kernel<<<(S_ * H_ * 3 + 255) / 256, 256>>>();
    kcvc_kernel<<<(C_ * G_ * DQ_) / 256, 256>>>();

    // Three attention branches, accumulating gated outputs into g_ocomb
    cmp_attn_kernel<<<dim3(S_, G_), 512>>>();
    slc_attn_kernel<<<dim3(S_, G_), 512>>>();
    win_attn_kernel<<<dim3(S_, G_), 512>>>();

    // Output projection
    gemm128<<<dim3(16, 8), 256>>>(p_ocomb, Wo, out, S_, D_, H_ * DV_);
}

// round 3
// speedup vs baseline: 1.9555x; 1.9555x over previous
#include <cuda_runtime.h>

// ---------------------------------------------------------------------------
// NSA forward. R2: fused projection GEMM (one launch) + f32x2 packed-FMA GEMM
// (double-buffered, BK=16, transposed A smem tile). Attention unchanged.
// ---------------------------------------------------------------------------

namespace {
constexpr int S_ = 1024;
constexpr int D_ = 2048;
constexpr int H_ = 32;
constexpr int G_ = 2;
constexpr int HG_ = 16;      // heads per group
constexpr int DQ_ = 128;
constexpr int DV_ = 128;
constexpr int BLK_ = 64;
constexpr int C_ = 16;       // S / BLK
constexpr int TOPN_ = 4;
constexpr int WIN_ = 256;
constexpr float SCALE_ = 0.08838834764831845f;  // 1/sqrt(128)
}

// Scratch (device globals; no allocation allowed)
__device__ float g_qraw[S_ * H_ * DQ_];
__device__ float g_q[S_ * H_ * DQ_];
__device__ float g_kraw[S_ * G_ * DQ_];
__device__ float g_k[S_ * G_ * DQ_];
__device__ float g_v[S_ * G_ * DV_];
__device__ float g_gates[S_ * H_ * 3];
__device__ float g_kc[C_ * G_ * DQ_];
__device__ float g_vc[C_ * G_ * DV_];
__device__ int   g_idx[S_ * G_ * TOPN_];
__device__ float g_ocomb[S_ * H_ * DV_];

__device__ __forceinline__ float warp_sum(float v) {
#pragma unroll
    for (int o = 16; o > 0; o >>= 1) v += __shfl_xor_sync(0xffffffffu, v, o);
    return v;
}
__device__ __forceinline__ float warp_max(float v) {
#pragma unroll
    for (int o = 16; o > 0; o >>= 1) v = fmaxf(v, __shfl_xor_sync(0xffffffffu, v, o));
    return v;
}

// ---- packed f32x2 helpers (sm_103a FFMA2 path; PTX-only) ------------------
__device__ __forceinline__ unsigned long long pack2_dup(float v) {
    unsigned long long r;
    asm("mov.b64 %0, {%1, %1};" : "=l"(r) : "f"(v));
    return r;
}
__device__ __forceinline__ void ffma2(unsigned long long& d, unsigned long long a,
                                      unsigned long long b) {
    asm("fma.rn.f32x2 %0, %1, %2, %0;" : "+l"(d) : "l"(a), "l"(b));
}
__device__ __forceinline__ void unpack2(unsigned long long p, float& lo, float& hi) {
    asm("mov.b64 {%0, %1}, %2;" : "=f"(lo), "=f"(hi) : "l"(p));
}

// ---------------------------------------------------------------------------
// GEMM tile body: C[128,128] block of A[M,K]@B[K,N]. 256 threads, BK=16,
// 8x8 microtile per thread computed as 8x(4 f32x2 pairs).
// As stored transposed [k][row] (pad 132) so a-reads are contiguous LDS.128.
// ---------------------------------------------------------------------------
struct SmemGemm {
    float As[2][16][132];
    float Bs[2][16][128];
};

__device__ __forceinline__ void gemm_tile(
    const float* __restrict__ A, int lda,
    const float* __restrict__ B, int ldb,
    float* __restrict__ C, int ldc,
    int K, int Nloc, int bm, int bn, SmemGemm& sm) {
    const int tid = threadIdx.x;
    const int arow = tid >> 1, acol = (tid & 1) * 8;
    const int brow = tid >> 4, bcol = (tid & 15) * 8;
    const int tx = (tid & 15) * 8, ty = (tid >> 4) * 8;

    const float* Abase = A + (size_t)(bm + arow) * lda + acol;
    const float* Bbase = B + (size_t)brow * ldb + bn + bcol;
    const bool bok0 = (bn + bcol + 3) < Nloc;
    const bool bok1 = (bn + bcol + 7) < Nloc;

    unsigned long long acc2[8][4];
#pragma unroll
    for (int i = 0; i < 8; i++)
#pragma unroll
        for (int j = 0; j < 4; j++) acc2[i][j] = 0ull;

    float4 ra0, ra1, rb0, rb1;
    const float4 fz = make_float4(0.f, 0.f, 0.f, 0.f);

    // load iter 0
    ra0 = *(const float4*)(Abase);
    ra1 = *(const float4*)(Abase + 4);
    rb0 = bok0 ? *(const float4*)(Bbase) : fz;
    rb1 = bok1 ? *(const float4*)(Bbase + 4) : fz;

    // STS iter 0 -> buf 0
    {
        sm.As[0][acol + 0][arow] = ra0.x;
        sm.As[0][acol + 1][arow] = ra0.y;
        sm.As[0][acol + 2][arow] = ra0.z;
        sm.As[0][acol + 3][arow] = ra0.w;
        sm.As[0][acol + 4][arow] = ra1.x;
        sm.As[0][acol + 5][arow] = ra1.y;
        sm.As[0][acol + 6][arow] = ra1.z;
        sm.As[0][acol + 7][arow] = ra1.w;
        *(float4*)&sm.Bs[0][brow][bcol] = rb0;
        *(float4*)&sm.Bs[0][brow][bcol + 4] = rb1;
    }
    __syncthreads();

    const int nIt = K >> 4;
    int buf = 0;
    for (int it = 0; it < nIt; ++it) {
        const bool more = (it + 1) < nIt;
        if (more) {
            const float* Ap = Abase + (it + 1) * 16;
            const float* Bp = Bbase + (size_t)(it + 1) * 16 * ldb;
            ra0 = *(const float4*)(Ap);
            ra1 = *(const float4*)(Ap + 4);
            rb0 = bok0 ? *(const float4*)(Bp) : fz;
            rb1 = bok1 ? *(const float4*)(Bp + 4) : fz;
        }
#pragma unroll
        for (int kk = 0; kk < 16; ++kk) {
            float4 av0 = *(const float4*)&sm.As[buf][kk][ty];
            float4 av1 = *(const float4*)&sm.As[buf][kk][ty + 4];
            ulonglong2 bp0 = *(const ulonglong2*)&sm.Bs[buf][kk][tx];
            ulonglong2 bp1 = *(const ulonglong2*)&sm.Bs[buf][kk][tx + 4];
            unsigned long long b2[4] = {bp0.x, bp0.y, bp1.x, bp1.y};
            float a[8] = {av0.x, av0.y, av0.z, av0.w, av1.x, av1.y, av1.z, av1.w};
#pragma unroll
            for (int i = 0; i < 8; i++) {
                unsigned long long a2 = pack2_dup(a[i]);
                ffma2(acc2[i][0], a2, b2[0]);
                ffma2(acc2[i][1], a2, b2[1]);
                ffma2(acc2[i][2], a2, b2[2]);
                ffma2(acc2[i][3], a2, b2[3]);
            }
        }
        if (more) {
            __syncthreads();
            const int nb = buf ^ 1;
            sm.As[nb][acol + 0][arow] = ra0.x;
            sm.As[nb][acol + 1][arow] = ra0.y;
            sm.As[nb][acol + 2][arow] = ra0.z;
            sm.As[nb][acol + 3][arow] = ra0.w;
            sm.As[nb][acol + 4][arow] = ra1.x;
            sm.As[nb][acol + 5][arow] = ra1.y;
            sm.As[nb][acol + 6][arow] = ra1.z;
            sm.As[nb][acol + 7][arow] = ra1.w;
            *(float4*)&sm.Bs[nb][brow][bcol] = rb0;
            *(float4*)&sm.Bs[nb][brow][bcol + 4] = rb1;
            __syncthreads();
            buf = nb;
        }
    }

    // epilogue
#pragma unroll
    for (int i = 0; i < 8; i++) {
        float* Crow = C + (size_t)(bm + ty + i) * ldc + bn + tx;
#pragma unroll
        for (int j = 0; j < 4; j++) {
            float lo, hi;
            unpack2(acc2[i][j], lo, hi);
            int col = bn + tx + 2 * j;
            if (col < Nloc) Crow[2 * j] = lo;
            if (col + 1 < Nloc) Crow[2 * j + 1] = hi;
        }
    }
}

// Fused Q/K/V/gate projections: blockIdx.x routes the n-tile.
__global__ __launch_bounds__(256) void fused_proj_kernel(
    const float* __restrict__ x,
    const float* __restrict__ Wq, const float* __restrict__ Wk,
    const float* __restrict__ Wv, const float* __restrict__ Wc,
    float* __restrict__ qraw, float* __restrict__ kraw,
    float* __restrict__ v, float* __restrict__ gates) {
    __shared__ SmemGemm sm;
    const int t = blockIdx.x;
    const int bm = blockIdx.y * 128;
    const float* B;
    float* Cp;
    int Nloc, bn;
    if (t < 32)      { B = Wq; Cp = qraw;  Nloc = 4096; bn = t * 128; }
    else if (t < 34) { B = Wk; Cp = kraw;  Nloc = 256;  bn = (t - 32) * 128; }
    else if (t < 36) { B = Wv; Cp = v;     Nloc = 256;  bn = (t - 34) * 128; }
    else             { B = Wc; Cp = gates; Nloc = 96;   bn = 0; }
    gemm_tile(x, D_, B, Nloc, Cp, Nloc, D_, Nloc, bm, bn, sm);
}

// Output projection: (S x 4096) @ (4096 x 2048)
__global__ __launch_bounds__(256) void gemm_out_kernel(
    const float* __restrict__ A, const float* __restrict__ Wo,
    float* __restrict__ out) {
    __shared__ SmemGemm sm;
    gemm_tile(A, H_ * DV_, Wo, D_, out, D_, H_ * DV_, D_,
              blockIdx.y * 128, blockIdx.x * 128, sm);
}

// ---------------------------------------------------------------------------
// RoPE
// ---------------------------------------------------------------------------
__global__ __launch_bounds__(256) void rope_q_kernel(const float* __restrict__ cosp,
                                                     const float* __restrict__ sinp) {
    int i = blockIdx.x * 256 + threadIdx.x;
    if (i >= S_ * H_ * DQ_) return;
    int d = i & 127;
    int s = i >> 12;
    float c = cosp[s * DQ_ + d], sn = sinp[s * DQ_ + d];
    float t = g_qraw[i];
    float rot = (d < 64) ? -g_qraw[i + 64] : g_qraw[i - 64];
    g_q[i] = t * c + rot * sn;
}

__global__ __launch_bounds__(256) void rope_k_kernel(const float* __restrict__ cosp,
                                                     const float* __restrict__ sinp) {
    int i = blockIdx.x * 256 + threadIdx.x;
    if (i >= S_ * G_ * DQ_) return;
    int d = i & 127;
    int s = i >> 8;
    float c = cosp[s * DQ_ + d], sn = sinp[s * DQ_ + d];
    float t = g_kraw[i];
    float rot = (d < 64) ? -g_kraw[i + 64] : g_kraw[i - 64];
    g_k[i] = t * c + rot * sn;
}

__global__ __launch_bounds__(256) void sigmoid_kernel() {
    int i = blockIdx.x * 256 + threadIdx.x;
    if (i >= S_ * H_ * 3) return;
    g_gates[i] = 1.f / (1.f + expf(-g_gates[i]));
}

// Block means of K/V per (c, g, d)
__global__ __launch_bounds__(256) void kcvc_kernel() {
    int i = blockIdx.x * 256 + threadIdx.x;
    if (i >= C_ * G_ * DQ_) return;
    int d = i & 127;
    int g = (i >> 7) & 1;
    int c = i >> 8;
    float sk = 0.f, sv = 0.f;
    for (int j = 0; j < BLK_; j++) {
        int t = c * BLK_ + j;
        sk += g_k[(t * G_ + g) * DQ_ + d];
        sv += g_v[(t * G_ + g) * DV_ + d];
    }
    g_kc[i] = sk * (1.f / 64.f);
    g_vc[i] = sv * (1.f / 64.f);
}

// ---------------------------------------------------------------------------
// Compressed attention + importance + stable top-4 selection.
// ---------------------------------------------------------------------------
__global__ __launch_bounds__(512) void cmp_attn_kernel() {
    const int s = blockIdx.x;
    const int g = blockIdx.y;
    __shared__ float kcs[C_][DQ_];
    __shared__ float vcs[C_][DQ_];
    __shared__ float pw[HG_][C_];
    const int tid = threadIdx.x;

    for (int i = tid; i < C_ * DQ_; i += 512) {
        int c = i >> 7, d = i & 127;
        kcs[c][d] = g_kc[(c * G_ + g) * DQ_ + d];
        vcs[c][d] = g_vc[(c * G_ + g) * DV_ + d];
    }
    __syncthreads();

    const int w = tid >> 5, l = tid & 31;
    const int h = g * HG_ + w;
    const float* qp = &g_q[(s * H_ + h) * DQ_];
    float q0 = qp[l], q1 = qp[l + 32], q2 = qp[l + 64], q3 = qp[l + 96];

    const int ncmp = (s + 1) >> 6;
    float logit[C_];
#pragma unroll
    for (int c = 0; c < C_; c++) {
        if (c < ncmp) {
            float part = q0 * kcs[c][l] + q1 * kcs[c][l + 32] +
                         q2 * kcs[c][l + 64] + q3 * kcs[c][l + 96];
            logit[c] = warp_sum(part) * SCALE_;
        } else {
            logit[c] = -1e30f;
        }
    }
    float m = -1e30f;
#pragma unroll
    for (int c = 0; c < C_; c++) m = fmaxf(m, logit[c]);
    float p[C_];
    float sum = 0.f;
#pragma unroll
    for (int c = 0; c < C_; c++) {
        float e = (logit[c] > -1e29f) ? expf(logit[c] - m) : 0.f;
        p[c] = e;
        sum += e;
    }
    float inv = (sum > 0.f) ? 1.f / sum : 0.f;

    float o0 = 0.f, o1 = 0.f, o2 = 0.f, o3 = 0.f;
#pragma unroll
    for (int c = 0; c < C_; c++) {
        float pc = p[c] * inv;
        o0 += pc * vcs[c][l];
        o1 += pc * vcs[c][l + 32];
        o2 += pc * vcs[c][l + 64];
        o3 += pc * vcs[c][l + 96];
        if (l == 0) pw[w][c] = pc;
    }
    float gate = g_gates[(s * H_ + h) * 3 + 0];
    float* op = &g_ocomb[(s * H_ + h) * DV_];
    op[l]      = gate * o0;
    op[l + 32] = gate * o1;
    op[l + 64] = gate * o2;
    op[l + 96] = gate * o3;
    __syncthreads();

    if (tid == 0) {
        const int cur = s >> 6;
        float imp[C_];
        for (int c = 0; c < C_; c++) {
            float v;
            if (c > cur) v = -1e9f;
            else if (c == 0 || c == cur) v = 1e9f;
            else {
                v = 0.f;
                for (int ww = 0; ww < HG_; ww++) v += pw[ww][c];
            }
            imp[c] = v;
        }
        bool tk[C_];
        for (int c = 0; c < C_; c++) tk[c] = false;
        for (int t = 0; t < TOPN_; t++) {
            float best = -3e38f;
            int bi = 0;
            for (int c = 0; c < C_; c++)
                if (!tk[c] && imp[c] > best) { best = imp[c]; bi = c; }
            tk[bi] = true;
            g_idx[(s * G_ + g) * TOPN_ + t] = bi;
        }
    }
}

// ---------------------------------------------------------------------------
// Selected attention over top-4 blocks.
// ---------------------------------------------------------------------------
__global__ __launch_bounds__(512) void slc_attn_kernel() {
    const int s = blockIdx.x, g = blockIdx.y;
    __shared__ float kv[DQ_][BLK_ + 1];
    __shared__ float qsh[HG_][DQ_];
    __shared__ int idxs[TOPN_];
    const int tid = threadIdx.x;

    for (int i = tid; i < HG_ * DQ_; i += 512)
        qsh[i >> 7][i & 127] = g_q[(s * H_ + g * HG_ + (i >> 7)) * DQ_ + (i & 127)];
    if (tid < TOPN_) idxs[tid] = g_idx[(s * G_ + g) * TOPN_ + tid];
    __syncthreads();

    const int w = tid >> 5, l = tid & 31;
    float ls[2 * TOPN_];

#pragma unroll
    for (int n = 0; n < TOPN_; n++) {
        const int t0 = idxs[n] * BLK_;
        for (int i = tid; i < BLK_ * DQ_; i += 512) {
            int j = i >> 7, d = i & 127;
            kv[d][j] = g_k[((t0 + j) * G_ + g) * DQ_ + d];
        }
        __syncthreads();
        float a0 = 0.f, a1 = 0.f;
#pragma unroll 8
        for (int d = 0; d < DQ_; d++) {
            float qd = qsh[w][d];
            a0 += qd * kv[d][l];
            a1 += qd * kv[d][l + 32];
        }
        ls[n * 2 + 0] = (t0 + l <= s) ? a0 * SCALE_ : -1e30f;
        ls[n * 2 + 1] = (t0 + l + 32 <= s) ? a1 * SCALE_ : -1e30f;
        __syncthreads();
    }

    float m = -1e30f;
#pragma unroll
    for (int r = 0; r < 2 * TOPN_; r++) m = fmaxf(m, ls[r]);
    m = warp_max(m);
    float sum = 0.f;
#pragma unroll
    for (int r = 0; r < 2 * TOPN_; r++) {
        ls[r] = (ls[r] > -1e29f) ? expf(ls[r] - m) : 0.f;
        sum += ls[r];
    }
    sum = warp_sum(sum);
    float inv = 1.f / sum;
#pragma unroll
    for (int r = 0; r < 2 * TOPN_; r++) ls[r] *= inv;

    float o0 = 0.f, o1 = 0.f, o2 = 0.f, o3 = 0.f;
#pragma unroll
    for (int n = 0; n < TOPN_; n++) {
        const int t0 = idxs[n] * BLK_;
        for (int i = tid; i < BLK_ * DV_; i += 512) {
            int j = i >> 7, d = i & 127;
            kv[d][j] = g_v[((t0 + j) * G_ + g) * DV_ + d];
        }
        __syncthreads();
#pragma unroll 4
        for (int j = 0; j < BLK_; j++) {
            float pj = __shfl_sync(0xffffffffu, ls[n * 2 + (j >> 5)], j & 31);
            o0 += pj * kv[l][j];
            o1 += pj * kv[l + 32][j];
            o2 += pj * kv[l + 64][j];
            o3 += pj * kv[l + 96][j];
        }
        __syncthreads();
    }

    const int h = g * HG_ + w;
    float gate = g_gates[(s * H_ + h) * 3 + 1];
    float* op = &g_ocomb[(s * H_ + h) * DV_];
    op[l]      += gate * o0;
    op[l + 32] += gate * o1;
    op[l + 64] += gate * o2;
    op[l + 96] += gate * o3;
}

// ---------------------------------------------------------------------------
// Sliding-window attention.
// ---------------------------------------------------------------------------
__global__ __launch_bounds__(512) void win_attn_kernel() {
    const int s = blockIdx.x, g = blockIdx.y;
    __shared__ float kv[DQ_][BLK_ + 1];
    __shared__ float qsh[HG_][DQ_];
    const int tid = threadIdx.x;

    for (int i = tid; i < HG_ * DQ_; i += 512)
        qsh[i >> 7][i & 127] = g_q[(s * H_ + g * HG_ + (i >> 7)) * DQ_ + (i & 127)];
    __syncthreads();

    const int w = tid >> 5, l = tid & 31;
    const int wstart = (s >= WIN_) ? (s - WIN_ + 1) : 0;
    float ls[8];

#pragma unroll
    for (int n = 0; n < 4; n++) {
        const int t0 = wstart + n * BLK_;
        for (int i = tid; i < BLK_ * DQ_; i += 512) {
            int j = i >> 7, d = i & 127;
            kv[d][j] = g_k[((t0 + j) * G_ + g) * DQ_ + d];
        }
        __syncthreads();
        float a0 = 0.f, a1 = 0.f;
#pragma unroll 8
        for (int d = 0; d < DQ_; d++) {
            float qd = qsh[w][d];
            a0 += qd * kv[d][l];
            a1 += qd * kv[d][l + 32];
        }
        ls[n * 2 + 0] = (t0 + l <= s) ? a0 * SCALE_ : -1e30f;
        ls[n * 2 + 1] = (t0 + l + 32 <= s) ? a1 * SCALE_ : -1e30f;
        __syncthreads();
    }

    float m = -1e30f;
#pragma unroll
    for (int r = 0; r < 8; r++) m = fmaxf(m, ls[r]);
    m = warp_max(m);
    float sum = 0.f;
#pragma unroll
    for (int r = 0; r < 8; r++) {
        ls[r] = (ls[r] > -1e29f) ? expf(ls[r] - m) : 0.f;
        sum += ls[r];
    }
    sum = warp_sum(sum);
    float inv = 1.f / sum;
#pragma unroll
    for (int r = 0; r < 8; r++) ls[r] *= inv;

    float o0 = 0.f, o1 = 0.f, o2 = 0.f, o3 = 0.f;
#pragma unroll
    for (int n = 0; n < 4; n++) {
        const int t0 = wstart + n * BLK_;
        for (int i = tid; i < BLK_ * DV_; i += 512) {
            int j = i >> 7, d = i & 127;
            kv[d][j] = g_v[((t0 + j) * G_ + g) * DV_ + d];
        }
        __syncthreads();
#pragma unroll 4
        for (int j = 0; j < BLK_; j++) {
            float pj = __shfl_sync(0xffffffffu, ls[n * 2 + (j >> 5)], j & 31);
            o0 += pj * kv[l][j];
            o1 += pj * kv[l + 32][j];
            o2 += pj * kv[l + 64][j];
            o3 += pj * kv[l + 96][j];
        }
        __syncthreads();
    }

    const int h = g * HG_ + w;
    float gate = g_gates[(s * H_ + h) * 3 + 2];
    float* op = &g_ocomb[(s * H_ + h) * DV_];
    op[l]      += gate * o0;
    op[l + 32] += gate * o1;
    op[l + 64] += gate * o2;
    op[l + 96] += gate * o3;
}

// ---------------------------------------------------------------------------
extern "C" void kernel_launch(void* const* d_in, const int* in_sizes, int n_in,
                              void* d_out, int out_size) {
    const float* x    = (const float*)d_in[0];
    const float* cosp = (const float*)d_in[1];
    const float* sinp = (const float*)d_in[2];
    const float* Wq   = (const float*)d_in[3];
    const float* Wk   = (const float*)d_in[4];
    const float* Wv   = (const float*)d_in[5];
    const float* Wo   = (const float*)d_in[6];
    const float* Wc   = (const float*)d_in[7];
    float* out = (float*)d_out;

    float *p_qraw, *p_kraw, *p_v, *p_gates, *p_ocomb;
    cudaGetSymbolAddress((void**)&p_qraw, g_qraw);
    cudaGetSymbolAddress((void**)&p_kraw, g_kraw);
    cudaGetSymbolAddress((void**)&p_v, g_v);
    cudaGetSymbolAddress((void**)&p_gates, g_gates);
    cudaGetSymbolAddress((void**)&p_ocomb, g_ocomb);

    // Fused projections: 37 n-tiles (32 Wq, 2 Wk, 2 Wv, 1 Wc) x 8 m-tiles
    fused_proj_kernel<<<dim3(37, 8), 256>>>(x, Wq, Wk, Wv, Wc,
                                            p_qraw, p_kraw, p_v, p_gates);

    // RoPE + gates + block means
    rope_q_kernel<<<(S_ * H_ * DQ_) / 256, 256>>>(cosp, sinp);
    rope_k_kernel<<<(S_ * G_ * DQ_) / 256, 256>>>(cosp, sinp);
    sigmoid_kernel<<<(S_ * H_ * 3 + 255) / 256, 256>>>();
    kcvc_kernel<<<(C_ * G_ * DQ_) / 256, 256>>>();

    // Three attention branches
    cmp_attn_kernel<<<dim3(S_, G_), 512>>>();
    slc_attn_kernel<<<dim3(S_, G_), 512>>>();
    win_attn_kernel<<<dim3(S_, G_), 512>>>();

    // Output projection
    gemm_out_kernel<<<dim3(16, 8), 256>>>(p_ocomb, Wo, out);
}

// round 4
// speedup vs baseline: 2.7896x; 1.4266x over previous
#include <cuda_runtime.h>
#include <cuda_bf16.h>

// ---------------------------------------------------------------------------
// NSA forward. R3: tensor-core GEMMs via mma.sync bf16 with hi/lo split
// (3-term, fp32-grade accuracy). Attention branches unchanged.
// ---------------------------------------------------------------------------

namespace {
constexpr int S_ = 1024;
constexpr int D_ = 2048;
constexpr int H_ = 32;
constexpr int G_ = 2;
constexpr int HG_ = 16;      // heads per group
constexpr int DQ_ = 128;
constexpr int DV_ = 128;
constexpr int BLK_ = 64;
constexpr int C_ = 16;       // S / BLK
constexpr int TOPN_ = 4;
constexpr int WIN_ = 256;
constexpr int NQ_ = H_ * DQ_;   // 4096
constexpr int NKV_ = G_ * DQ_;  // 256
constexpr int NC_ = H_ * 3;     // 96
constexpr float SCALE_ = 0.08838834764831845f;  // 1/sqrt(128)
}

// fp32 scratch
__device__ float g_qraw[S_ * NQ_];
__device__ float g_q[S_ * NQ_];
__device__ float g_kraw[S_ * NKV_];
__device__ float g_k[S_ * NKV_];
__device__ float g_v[S_ * NKV_];
__device__ float g_gates[S_ * NC_];
__device__ float g_kc[C_ * G_ * DQ_];
__device__ float g_vc[C_ * G_ * DV_];
__device__ int   g_idx[S_ * G_ * TOPN_];
__device__ float g_ocomb[S_ * H_ * DV_];

// bf16 split planes
__device__ __align__(16) __nv_bfloat16 g_xh[S_ * D_],  g_xl[S_ * D_];
__device__ __align__(16) __nv_bfloat16 g_Wqh[D_ * NQ_], g_Wql[D_ * NQ_];
__device__ __align__(16) __nv_bfloat16 g_Wkh[D_ * NKV_], g_Wkl[D_ * NKV_];
__device__ __align__(16) __nv_bfloat16 g_Wvh[D_ * NKV_], g_Wvl[D_ * NKV_];
__device__ __align__(16) __nv_bfloat16 g_Wch[D_ * NC_],  g_Wcl[D_ * NC_];
__device__ __align__(16) __nv_bfloat16 g_Woh[H_ * DV_ * D_], g_Wol[H_ * DV_ * D_];
__device__ __align__(16) __nv_bfloat16 g_oh[S_ * H_ * DV_], g_ol[S_ * H_ * DV_];

__device__ __forceinline__ float warp_sum(float v) {
#pragma unroll
    for (int o = 16; o > 0; o >>= 1) v += __shfl_xor_sync(0xffffffffu, v, o);
    return v;
}
__device__ __forceinline__ float warp_max(float v) {
#pragma unroll
    for (int o = 16; o > 0; o >>= 1) v = fmaxf(v, __shfl_xor_sync(0xffffffffu, v, o));
    return v;
}

// ---- tensor-core primitives ------------------------------------------------
__device__ __forceinline__ void ldsm_x4(unsigned (&r)[4], unsigned saddr) {
    asm volatile("ldmatrix.sync.aligned.m8n8.x4.shared.b16 {%0,%1,%2,%3}, [%4];"
                 : "=r"(r[0]), "=r"(r[1]), "=r"(r[2]), "=r"(r[3]) : "r"(saddr));
}
__device__ __forceinline__ void ldsm_x4_t(unsigned (&r)[4], unsigned saddr) {
    asm volatile("ldmatrix.sync.aligned.m8n8.x4.trans.shared.b16 {%0,%1,%2,%3}, [%4];"
                 : "=r"(r[0]), "=r"(r[1]), "=r"(r[2]), "=r"(r[3]) : "r"(saddr));
}
__device__ __forceinline__ void mma_bf16(float (&c)[4], const unsigned (&a)[4],
                                         unsigned b0, unsigned b1) {
    asm volatile(
        "mma.sync.aligned.m16n8k16.row.col.f32.bf16.bf16.f32 "
        "{%0,%1,%2,%3}, {%4,%5,%6,%7}, {%8,%9}, {%0,%1,%2,%3};"
        : "+f"(c[0]), "+f"(c[1]), "+f"(c[2]), "+f"(c[3])
        : "r"(a[0]), "r"(a[1]), "r"(a[2]), "r"(a[3]), "r"(b0), "r"(b1));
}

// ---------------------------------------------------------------------------
// Split fp32 -> bf16 hi + bf16 lo (residual)
// ---------------------------------------------------------------------------
__global__ __launch_bounds__(256) void cvt_split_kernel(
    const float* __restrict__ src, __nv_bfloat16* __restrict__ hi,
    __nv_bfloat16* __restrict__ lo, int n4) {
    int i = blockIdx.x * 256 + threadIdx.x;
    if (i >= n4) return;
    float4 v = ((const float4*)src)[i];
    __nv_bfloat16 h0 = __float2bfloat16(v.x);
    __nv_bfloat16 h1 = __float2bfloat16(v.y);
    __nv_bfloat16 h2 = __float2bfloat16(v.z);
    __nv_bfloat16 h3 = __float2bfloat16(v.w);
    __nv_bfloat16 l0 = __float2bfloat16(v.x - __bfloat162float(h0));
    __nv_bfloat16 l1 = __float2bfloat16(v.y - __bfloat162float(h1));
    __nv_bfloat16 l2 = __float2bfloat16(v.z - __bfloat162float(h2));
    __nv_bfloat16 l3 = __float2bfloat16(v.w - __bfloat162float(h3));
    __nv_bfloat162* hp = (__nv_bfloat162*)hi;
    __nv_bfloat162* lp = (__nv_bfloat162*)lo;
    __nv_bfloat162 a, b;
    a.x = h0; a.y = h1; b.x = h2; b.y = h3;
    hp[i * 2] = a; hp[i * 2 + 1] = b;
    a.x = l0; a.y = l1; b.x = l2; b.y = l3;
    lp[i * 2] = a; lp[i * 2 + 1] = b;
}

// ---------------------------------------------------------------------------
// MMA GEMM tile: C[128,128] of A[M,K]@B[K,N] using split bf16 planes.
// 256 threads = 8 warps (4m x 2n). K-step 32, ldmatrix + m16n8k16 bf16 mma.
// ---------------------------------------------------------------------------
struct SmemMMA {
    __nv_bfloat16 Ah[128][40];   // pad: stride 80B, conflict-free ldsm
    __nv_bfloat16 Al[128][40];
    __nv_bfloat16 Bh[32][136];   // pad: stride 272B, conflict-free ldsm.trans
    __nv_bfloat16 Bl[32][136];
};

__device__ __forceinline__ void gemm_tile_mma(
    const __nv_bfloat16* __restrict__ Agh, const __nv_bfloat16* __restrict__ Agl,
    int lda,
    const __nv_bfloat16* __restrict__ Bgh, const __nv_bfloat16* __restrict__ Bgl,
    int ldb,
    float* __restrict__ Cp, int ldc,
    int K, int Nloc, int bm, int bn, SmemMMA& sm) {
    const int tid = threadIdx.x;
    const int lane = tid & 31;
    const int w = tid >> 5;
    const int wm = (w >> 1) * 32;
    const int wn = (w & 1) * 64;

    // load assignments (16B chunks)
    const int ar0 = tid >> 2, ac0 = tid & 3;        // A rows 0..63
    const int ar1 = ar0 + 64;                       // A rows 64..127
    const int br0 = tid >> 4, bc0 = tid & 15;       // B rows 0..15
    const int br1 = br0 + 16;                       // B rows 16..31
    const bool bok = (bn + bc0 * 8 + 7) < Nloc;

    const unsigned sAh = (unsigned)__cvta_generic_to_shared(&sm.Ah[0][0]);
    const unsigned sAl = (unsigned)__cvta_generic_to_shared(&sm.Al[0][0]);
    const unsigned sBh = (unsigned)__cvta_generic_to_shared(&sm.Bh[0][0]);
    const unsigned sBl = (unsigned)__cvta_generic_to_shared(&sm.Bl[0][0]);

    float c[2][8][4];
#pragma unroll
    for (int i = 0; i < 2; i++)
#pragma unroll
        for (int j = 0; j < 8; j++)
#pragma unroll
            for (int q = 0; q < 4; q++) c[i][j][q] = 0.f;

    uint4 rA0h, rA1h, rA0l, rA1l, rB0h, rB1h, rB0l, rB1l;
    const uint4 uz = make_uint4(0u, 0u, 0u, 0u);

    auto load_tiles = [&](int k0) {
        const __nv_bfloat16* a0 = Agh + (size_t)(bm + ar0) * lda + k0 + ac0 * 8;
        const __nv_bfloat16* a1 = Agh + (size_t)(bm + ar1) * lda + k0 + ac0 * 8;
        const __nv_bfloat16* a2 = Agl + (size_t)(bm + ar0) * lda + k0 + ac0 * 8;
        const __nv_bfloat16* a3 = Agl + (size_t)(bm + ar1) * lda + k0 + ac0 * 8;
        rA0h = *(const uint4*)a0;
        rA1h = *(const uint4*)a1;
        rA0l = *(const uint4*)a2;
        rA1l = *(const uint4*)a3;
        if (bok) {
            const __nv_bfloat16* b0 = Bgh + (size_t)(k0 + br0) * ldb + bn + bc0 * 8;
            const __nv_bfloat16* b1 = Bgh + (size_t)(k0 + br1) * ldb + bn + bc0 * 8;
            const __nv_bfloat16* b2 = Bgl + (size_t)(k0 + br0) * ldb + bn + bc0 * 8;
            const __nv_bfloat16* b3 = Bgl + (size_t)(k0 + br1) * ldb + bn + bc0 * 8;
            rB0h = *(const uint4*)b0;
            rB1h = *(const uint4*)b1;
            rB0l = *(const uint4*)b2;
            rB1l = *(const uint4*)b3;
        } else {
            rB0h = uz; rB1h = uz; rB0l = uz; rB1l = uz;
        }
    };

    load_tiles(0);
    const int nSteps = K >> 5;
    for (int step = 0; step < nSteps; step++) {
        // stage to smem
        *(uint4*)&sm.Ah[ar0][ac0 * 8] = rA0h;
        *(uint4*)&sm.Ah[ar1][ac0 * 8] = rA1h;
        *(uint4*)&sm.Al[ar0][ac0 * 8] = rA0l;
        *(uint4*)&sm.Al[ar1][ac0 * 8] = rA1l;
        *(uint4*)&sm.Bh[br0][bc0 * 8] = rB0h;
        *(uint4*)&sm.Bh[br1][bc0 * 8] = rB1h;
        *(uint4*)&sm.Bl[br0][bc0 * 8] = rB0l;
        *(uint4*)&sm.Bl[br1][bc0 * 8] = rB1l;
        __syncthreads();

        if (step + 1 < nSteps) load_tiles((step + 1) * 32);  // prefetch

#pragma unroll
        for (int kk = 0; kk < 2; kk++) {
            unsigned ah[2][4], al[2][4], bh[4][4], bl[4][4];
#pragma unroll
            for (int i = 0; i < 2; i++) {
                unsigned arow = wm + 16 * i + (lane & 15);
                unsigned achunk = kk * 2 + (lane >> 4);
                unsigned off = (arow * 40 + achunk * 8) * 2;
                ldsm_x4(ah[i], sAh + off);
                ldsm_x4(al[i], sAl + off);
            }
#pragma unroll
            for (int j = 0; j < 4; j++) {
                unsigned brow = kk * 16 + (lane & 15);
                unsigned bcol = wn + 16 * j + 8 * (lane >> 4);
                unsigned off = (brow * 136 + bcol) * 2;
                ldsm_x4_t(bh[j], sBh + off);
                ldsm_x4_t(bl[j], sBl + off);
            }
#pragma unroll
            for (int i = 0; i < 2; i++) {
#pragma unroll
                for (int jn = 0; jn < 8; jn++) {
                    const int j = jn >> 1, p = (jn & 1) * 2;
                    mma_bf16(c[i][jn], ah[i], bh[j][p], bh[j][p + 1]);
                    mma_bf16(c[i][jn], ah[i], bl[j][p], bl[j][p + 1]);
                    mma_bf16(c[i][jn], al[i], bh[j][p], bh[j][p + 1]);
                }
            }
        }
        __syncthreads();
    }

    // epilogue
    const int qrow = lane >> 2;
    const int qcol = (lane & 3) * 2;
#pragma unroll
    for (int i = 0; i < 2; i++) {
        const int row0 = bm + wm + 16 * i + qrow;
#pragma unroll
        for (int jn = 0; jn < 8; jn++) {
            const int col = bn + wn + jn * 8 + qcol;
            if (col < Nloc) {
                float2 v0 = make_float2(c[i][jn][0], c[i][jn][1]);
                float2 v1 = make_float2(c[i][jn][2], c[i][jn][3]);
                *(float2*)&Cp[(size_t)row0 * ldc + col] = v0;
                *(float2*)&Cp[(size_t)(row0 + 8) * ldc + col] = v1;
            }
        }
    }
}

// Fused projections: blockIdx.x routes n-tile to Wq/Wk/Wv/Wc.
__global__ __launch_bounds__(256) void fused_proj_mma(
    float* __restrict__ qraw, float* __restrict__ kraw,
    float* __restrict__ v, float* __restrict__ gates) {
    __shared__ SmemMMA sm;
    const int t = blockIdx.x;
    const int bm = blockIdx.y * 128;
    const __nv_bfloat16 *Bh, *Bl;
    float* Cp;
    int Nloc, bn;
    if (t < 32)      { Bh = g_Wqh; Bl = g_Wql; Cp = qraw;  Nloc = NQ_;  bn = t * 128; }
    else if (t < 34) { Bh = g_Wkh; Bl = g_Wkl; Cp = kraw;  Nloc = NKV_; bn = (t - 32) * 128; }
    else if (t < 36) { Bh = g_Wvh; Bl = g_Wvl; Cp = v;     Nloc = NKV_; bn = (t - 34) * 128; }
    else             { Bh = g_Wch; Bl = g_Wcl; Cp = gates; Nloc = NC_;  bn = 0; }
    gemm_tile_mma(g_xh, g_xl, D_, Bh, Bl, Nloc, Cp, Nloc, D_, Nloc, bm, bn, sm);
}

__global__ __launch_bounds__(256) void gemm_out_mma(float* __restrict__ out) {
    __shared__ SmemMMA sm;
    gemm_tile_mma(g_oh, g_ol, H_ * DV_, g_Woh, g_Wol, D_, out, D_,
                  H_ * DV_, D_, blockIdx.y * 128, blockIdx.x * 128, sm);
}

// ---------------------------------------------------------------------------
// RoPE / sigmoid / block means
// ---------------------------------------------------------------------------
__global__ __launch_bounds__(256) void rope_q_kernel(const float* __restrict__ cosp,
                                                     const float* __restrict__ sinp) {
    int i = blockIdx.x * 256 + threadIdx.x;
    if (i >= S_ * H_ * DQ_) return;
    int d = i & 127;
    int s = i >> 12;
    float c = cosp[s * DQ_ + d], sn = sinp[s * DQ_ + d];
    float t = g_qraw[i];
    float rot = (d < 64) ? -g_qraw[i + 64] : g_qraw[i - 64];
    g_q[i] = t * c + rot * sn;
}

__global__ __launch_bounds__(256) void rope_k_kernel(const float* __restrict__ cosp,
                                                     const float* __restrict__ sinp) {
    int i = blockIdx.x * 256 + threadIdx.x;
    if (i >= S_ * G_ * DQ_) return;
    int d = i & 127;
    int s = i >> 8;
    float c = cosp[s * DQ_ + d], sn = sinp[s * DQ_ + d];
    float t = g_kraw[i];
    float rot = (d < 64) ? -g_kraw[i + 64] : g_kraw[i - 64];
    g_k[i] = t * c + rot * sn;
}

__global__ __launch_bounds__(256) void sigmoid_kernel() {
    int i = blockIdx.x * 256 + threadIdx.x;
    if (i >= S_ * NC_) return;
    g_gates[i] = 1.f / (1.f + expf(-g_gates[i]));
}

__global__ __launch_bounds__(256) void kcvc_kernel() {
    int i = blockIdx.x * 256 + threadIdx.x;
    if (i >= C_ * G_ * DQ_) return;
    int d = i & 127;
    int g = (i >> 7) & 1;
    int c = i >> 8;
    float sk = 0.f, sv = 0.f;
    for (int j = 0; j < BLK_; j++) {
        int t = c * BLK_ + j;
        sk += g_k[(t * G_ + g) * DQ_ + d];
        sv += g_v[(t * G_ + g) * DV_ + d];
    }
    g_kc[i] = sk * (1.f / 64.f);
    g_vc[i] = sv * (1.f / 64.f);
}

// ---------------------------------------------------------------------------
// Compressed attention + importance + stable top-4 selection.
// ---------------------------------------------------------------------------
__global__ __launch_bounds__(512) void cmp_attn_kernel() {
    const int s = blockIdx.x;
    const int g = blockIdx.y;
    __shared__ float kcs[C_][DQ_];
    __shared__ float vcs[C_][DQ_];
    __shared__ float pw[HG_][C_];
    const int tid = threadIdx.x;

    for (int i = tid; i < C_ * DQ_; i += 512) {
        int c = i >> 7, d = i & 127;
        kcs[c][d] = g_kc[(c * G_ + g) * DQ_ + d];
        vcs[c][d] = g_vc[(c * G_ + g) * DV_ + d];
    }
    __syncthreads();

    const int w = tid >> 5, l = tid & 31;
    const int h = g * HG_ + w;
    const float* qp = &g_q[(s * H_ + h) * DQ_];
    float q0 = qp[l], q1 = qp[l + 32], q2 = qp[l + 64], q3 = qp[l + 96];

    const int ncmp = (s + 1) >> 6;
    float logit[C_];
#pragma unroll
    for (int c = 0; c < C_; c++) {
        if (c < ncmp) {
            float part = q0 * kcs[c][l] + q1 * kcs[c][l + 32] +
                         q2 * kcs[c][l + 64] + q3 * kcs[c][l + 96];
            logit[c] = warp_sum(part) * SCALE_;
        } else {
            logit[c] = -1e30f;
        }
    }
    float m = -1e30f;
#pragma unroll
    for (int c = 0; c < C_; c++) m = fmaxf(m, logit[c]);
    float p[C_];
    float sum = 0.f;
#pragma unroll
    for (int c = 0; c < C_; c++) {
        float e = (logit[c] > -1e29f) ? expf(logit[c] - m) : 0.f;
        p[c] = e;
        sum += e;
    }
    float inv = (sum > 0.f) ? 1.f / sum : 0.f;

    float o0 = 0.f, o1 = 0.f, o2 = 0.f, o3 = 0.f;
#pragma unroll
    for (int c = 0; c < C_; c++) {
        float pc = p[c] * inv;
        o0 += pc * vcs[c][l];
        o1 += pc * vcs[c][l + 32];
        o2 += pc * vcs[c][l + 64];
        o3 += pc * vcs[c][l + 96];
        if (l == 0) pw[w][c] = pc;
    }
    float gate = g_gates[(s * H_ + h) * 3 + 0];
    float* op = &g_ocomb[(s * H_ + h) * DV_];
    op[l]      = gate * o0;
    op[l + 32] = gate * o1;
    op[l + 64] = gate * o2;
    op[l + 96] = gate * o3;
    __syncthreads();

    if (tid == 0) {
        const int cur = s >> 6;
        float imp[C_];
        for (int c = 0; c < C_; c++) {
            float v;
            if (c > cur) v = -1e9f;
            else if (c == 0 || c == cur) v = 1e9f;
            else {
                v = 0.f;
                for (int ww = 0; ww < HG_; ww++) v += pw[ww][c];
            }
            imp[c] = v;
        }
        bool tk[C_];
        for (int c = 0; c < C_; c++) tk[c] = false;
        for (int t = 0; t < TOPN_; t++) {
            float best = -3e38f;
            int bi = 0;
            for (int c = 0; c < C_; c++)
                if (!tk[c] && imp[c] > best) { best = imp[c]; bi = c; }
            tk[bi] = true;
            g_idx[(s * G_ + g) * TOPN_ + t] = bi;
        }
    }
}

// ---------------------------------------------------------------------------
// Selected attention over top-4 blocks.
// ---------------------------------------------------------------------------
__global__ __launch_bounds__(512) void slc_attn_kernel() {
    const int s = blockIdx.x, g = blockIdx.y;
    __shared__ float kv[DQ_][BLK_ + 1];
    __shared__ float qsh[HG_][DQ_];
    __shared__ int idxs[TOPN_];
    const int tid = threadIdx.x;

    for (int i = tid; i < HG_ * DQ_; i += 512)
        qsh[i >> 7][i & 127] = g_q[(s * H_ + g * HG_ + (i >> 7)) * DQ_ + (i & 127)];
    if (tid < TOPN_) idxs[tid] = g_idx[(s * G_ + g) * TOPN_ + tid];
    __syncthreads();

    const int w = tid >> 5, l = tid & 31;
    float ls[2 * TOPN_];

#pragma unroll
    for (int n = 0; n < TOPN_; n++) {
        const int t0 = idxs[n] * BLK_;
        for (int i = tid; i < BLK_ * DQ_; i += 512) {
            int j = i >> 7, d = i & 127;
            kv[d][j] = g_k[((t0 + j) * G_ + g) * DQ_ + d];
        }
        __syncthreads();
        float a0 = 0.f, a1 = 0.f;
#pragma unroll 8
        for (int d = 0; d < DQ_; d++) {
            float qd = qsh[w][d];
            a0 += qd * kv[d][l];
            a1 += qd * kv[d][l + 32];
        }
        ls[n * 2 + 0] = (t0 + l <= s) ? a0 * SCALE_ : -1e30f;
        ls[n * 2 + 1] = (t0 + l + 32 <= s) ? a1 * SCALE_ : -1e30f;
        __syncthreads();
    }

    float m = -1e30f;
#pragma unroll
    for (int r = 0; r < 2 * TOPN_; r++) m = fmaxf(m, ls[r]);
    m = warp_max(m);
    float sum = 0.f;
#pragma unroll
    for (int r = 0; r < 2 * TOPN_; r++) {
        ls[r] = (ls[r] > -1e29f) ? expf(ls[r] - m) : 0.f;
        sum += ls[r];
    }
    sum = warp_sum(sum);
    float inv = 1.f / sum;
#pragma unroll
    for (int r = 0; r < 2 * TOPN_; r++) ls[r] *= inv;

    float o0 = 0.f, o1 = 0.f, o2 = 0.f, o3 = 0.f;
#pragma unroll
    for (int n = 0; n < TOPN_; n++) {
        const int t0 = idxs[n] * BLK_;
        for (int i = tid; i < BLK_ * DV_; i += 512) {
            int j = i >> 7, d = i & 127;
            kv[d][j] = g_v[((t0 + j) * G_ + g) * DV_ + d];
        }
        __syncthreads();
#pragma unroll 4
        for (int j = 0; j < BLK_; j++) {
            float pj = __shfl_sync(0xffffffffu, ls[n * 2 + (j >> 5)], j & 31);
            o0 += pj * kv[l][j];
            o1 += pj * kv[l + 32][j];
            o2 += pj * kv[l + 64][j];
            o3 += pj * kv[l + 96][j];
        }
        __syncthreads();
    }

    const int h = g * HG_ + w;
    float gate = g_gates[(s * H_ + h) * 3 + 1];
    float* op = &g_ocomb[(s * H_ + h) * DV_];
    op[l]      += gate * o0;
    op[l + 32] += gate * o1;
    op[l + 64] += gate * o2;
    op[l + 96] += gate * o3;
}

// ---------------------------------------------------------------------------
// Sliding-window attention.
// ---------------------------------------------------------------------------
__global__ __launch_bounds__(512) void win_attn_kernel() {
    const int s = blockIdx.x, g = blockIdx.y;
    __shared__ float kv[DQ_][BLK_ + 1];
    __shared__ float qsh[HG_][DQ_];
    const int tid = threadIdx.x;

    for (int i = tid; i < HG_ * DQ_; i += 512)
        qsh[i >> 7][i & 127] = g_q[(s * H_ + g * HG_ + (i >> 7)) * DQ_ + (i & 127)];
    __syncthreads();

    const int w = tid >> 5, l = tid & 31;
    const int wstart = (s >= WIN_) ? (s - WIN_ + 1) : 0;
    float ls[8];

#pragma unroll
    for (int n = 0; n < 4; n++) {
        const int t0 = wstart + n * BLK_;
        for (int i = tid; i < BLK_ * DQ_; i += 512) {
            int j = i >> 7, d = i & 127;
            kv[d][j] = g_k[((t0 + j) * G_ + g) * DQ_ + d];
        }
        __syncthreads();
        float a0 = 0.f, a1 = 0.f;
#pragma unroll 8
        for (int d = 0; d < DQ_; d++) {
            float qd = qsh[w][d];
            a0 += qd * kv[d][l];
            a1 += qd * kv[d][l + 32];
        }
        ls[n * 2 + 0] = (t0 + l <= s) ? a0 * SCALE_ : -1e30f;
        ls[n * 2 + 1] = (t0 + l + 32 <= s) ? a1 * SCALE_ : -1e30f;
        __syncthreads();
    }

    float m = -1e30f;
#pragma unroll
    for (int r = 0; r < 8; r++) m = fmaxf(m, ls[r]);
    m = warp_max(m);
    float sum = 0.f;
#pragma unroll
    for (int r = 0; r < 8; r++) {
        ls[r] = (ls[r] > -1e29f) ? expf(ls[r] - m) : 0.f;
        sum += ls[r];
    }
    sum = warp_sum(sum);
    float inv = 1.f / sum;
#pragma unroll
    for (int r = 0; r < 8; r++) ls[r] *= inv;

    float o0 = 0.f, o1 = 0.f, o2 = 0.f, o3 = 0.f;
#pragma unroll
    for (int n = 0; n < 4; n++) {
        const int t0 = wstart + n * BLK_;
        for (int i = tid; i < BLK_ * DV_; i += 512) {
            int j = i >> 7, d = i & 127;
            kv[d][j] = g_v[((t0 + j) * G_ + g) * DV_ + d];
        }
        __syncthreads();
#pragma unroll 4
        for (int j = 0; j < BLK_; j++) {
            float pj = __shfl_sync(0xffffffffu, ls[n * 2 + (j >> 5)], j & 31);
            o0 += pj * kv[l][j];
            o1 += pj * kv[l + 32][j];
            o2 += pj * kv[l + 64][j];
            o3 += pj * kv[l + 96][j];
        }
        __syncthreads();
    }

    const int h = g * HG_ + w;
    float gate = g_gates[(s * H_ + h) * 3 + 2];
    float* op = &g_ocomb[(s * H_ + h) * DV_];
    op[l]      += gate * o0;
    op[l + 32] += gate * o1;
    op[l + 64] += gate * o2;
    op[l + 96] += gate * o3;
}

// ---------------------------------------------------------------------------
extern "C" void kernel_launch(void* const* d_in, const int* in_sizes, int n_in,
                              void* d_out, int out_size) {
    const float* x    = (const float*)d_in[0];
    const float* cosp = (const float*)d_in[1];
    const float* sinp = (const float*)d_in[2];
    const float* Wq   = (const float*)d_in[3];
    const float* Wk   = (const float*)d_in[4];
    const float* Wv   = (const float*)d_in[5];
    const float* Wo   = (const float*)d_in[6];
    const float* Wc   = (const float*)d_in[7];
    float* out = (float*)d_out;

    float *p_qraw, *p_kraw, *p_v, *p_gates, *p_ocomb;
    cudaGetSymbolAddress((void**)&p_qraw, g_qraw);
    cudaGetSymbolAddress((void**)&p_kraw, g_kraw);
    cudaGetSymbolAddress((void**)&p_v, g_v);
    cudaGetSymbolAddress((void**)&p_gates, g_gates);
    cudaGetSymbolAddress((void**)&p_ocomb, g_ocomb);

    __nv_bfloat16 *p_xh, *p_xl, *p_Wqh, *p_Wql, *p_Wkh, *p_Wkl;
    __nv_bfloat16 *p_Wvh, *p_Wvl, *p_Wch, *p_Wcl, *p_Woh, *p_Wol, *p_oh, *p_ol;
    cudaGetSymbolAddress((void**)&p_xh, g_xh);
    cudaGetSymbolAddress((void**)&p_xl, g_xl);
    cudaGetSymbolAddress((void**)&p_Wqh, g_Wqh);
    cudaGetSymbolAddress((void**)&p_Wql, g_Wql);
    cudaGetSymbolAddress((void**)&p_Wkh, g_Wkh);
    cudaGetSymbolAddress((void**)&p_Wkl, g_Wkl);
    cudaGetSymbolAddress((void**)&p_Wvh, g_Wvh);
    cudaGetSymbolAddress((void**)&p_Wvl, g_Wvl);
    cudaGetSymbolAddress((void**)&p_Wch, g_Wch);
    cudaGetSymbolAddress((void**)&p_Wcl, g_Wcl);
    cudaGetSymbolAddress((void**)&p_Woh, g_Woh);
    cudaGetSymbolAddress((void**)&p_Wol, g_Wol);
    cudaGetSymbolAddress((void**)&p_oh, g_oh);
    cudaGetSymbolAddress((void**)&p_ol, g_ol);

    auto cvt = [](const float* src, __nv_bfloat16* hi, __nv_bfloat16* lo, int n) {
        int n4 = n / 4;
        cvt_split_kernel<<<(n4 + 255) / 256, 256>>>(src, hi, lo, n4);
    };

    // splits for projection inputs
    cvt(x, p_xh, p_xl, S_ * D_);
    cvt(Wq, p_Wqh, p_Wql, D_ * NQ_);
    cvt(Wk, p_Wkh, p_Wkl, D_ * NKV_);
    cvt(Wv, p_Wvh, p_Wvl, D_ * NKV_);
    cvt(Wc, p_Wch, p_Wcl, D_ * NC_);
    cvt(Wo, p_Woh, p_Wol, H_ * DV_ * D_);

    // Fused projections: 37 n-tiles x 8 m-tiles, tensor cores
    fused_proj_mma<<<dim3(37, 8), 256>>>(p_qraw, p_kraw, p_v, p_gates);

    // RoPE + gates + block means
    rope_q_kernel<<<(S_ * H_ * DQ_) / 256, 256>>>(cosp, sinp);
    rope_k_kernel<<<(S_ * G_ * DQ_) / 256, 256>>>(cosp, sinp);
    sigmoid_kernel<<<(S_ * NC_ + 255) / 256, 256>>>();
    kcvc_kernel<<<(C_ * G_ * DQ_) / 256, 256>>>();

    // Three attention branches
    cmp_attn_kernel<<<dim3(S_, G_), 512>>>();
    slc_attn_kernel<<<dim3(S_, G_), 512>>>();
    win_attn_kernel<<<dim3(S_, G_), 512>>>();

    // split ocomb, then output projection on tensor cores
    cvt(p_ocomb, p_oh, p_ol, S_ * H_ * DV_);
    gemm_out_mma<<<dim3(16, 8), 256>>>(out);
}